// round 9
// baseline (speedup 1.0000x reference)
#include <cuda_runtime.h>
#include <cuda_fp16.h>

#define N_NODES 50000
#define N_EDGES 800000
#define N_GRAPHS 512
#define SCAN_BLOCKS 49  // ceil(50000/1024)
#define NBUCKET 128

// ---------------- scratch (static device globals; no allocs) ----------------
__device__ __half g_xlh[N_NODES * 64];   // fp16 mirror of xl (gathered in agg)
__device__ float g_xr[N_NODES * 64];
__device__ float g_h[N_NODES * 64];
__device__ int   g_rowptr[N_NODES + 1];
__device__ int   g_cnt[N_NODES];
__device__ int   g_incl[N_NODES];
__device__ int   g_part[64];
__device__ int   g_bucket[NBUCKET];   // degree histogram
__device__ int   g_boff[NBUCKET];     // degree bucket offsets (consumed atomically)
__device__ int   g_perm[N_NODES];     // nodes sorted by degree
__device__ float4 g_epack[N_EDGES];   // {ea0, ea1, ea2, __int_as_float(src)} sorted by dst
__device__ float g_wvec[64];
__device__ float g_cconst;
__device__ float g_gsum[N_GRAPHS];
__device__ int   g_gcnt[N_GRAPHS];

// ---------------- init: zero counters + precompute head vector ----------------
__global__ void k_init(const float* __restrict__ Wjk, const float* __restrict__ bjk,
                       const float* __restrict__ Whead, const float* __restrict__ bhead) {
    int i = blockIdx.x * blockDim.x + threadIdx.x;
    if (i < N_NODES) g_cnt[i] = 0;
    if (i < NBUCKET) g_bucket[i] = 0;
    if (i < N_GRAPHS) { g_gsum[i] = 0.f; g_gcnt[i] = 0; }
    if (i < 64) {
        float s = 0.f;
        for (int j = 0; j < 64; ++j) s += Wjk[i * 64 + j] * Whead[j];
        g_wvec[i] = s;
    }
    if (i == 0) {
        float s = 0.f;
        for (int j = 0; j < 64; ++j) s += bjk[j] * Whead[j];
        g_cconst = s + bhead[0];
    }
}

__global__ void k_hist(const int* __restrict__ ei) {
    int e = blockIdx.x * blockDim.x + threadIdx.x;
    if (e < N_EDGES) atomicAdd(&g_cnt[ei[N_EDGES + e]], 1);
}

// block-level inclusive scan of degrees + degree-bucket histogram
__global__ void k_scanA() {
    __shared__ int s[1024];
    int t = threadIdx.x;
    int i = blockIdx.x * 1024 + t;
    int v = (i < N_NODES) ? g_cnt[i] : 0;
    if (i < N_NODES) atomicAdd(&g_bucket[v < NBUCKET ? v : NBUCKET - 1], 1);
    s[t] = v;
    __syncthreads();
    for (int off = 1; off < 1024; off <<= 1) {
        int x = (t >= off) ? s[t - off] : 0;
        __syncthreads();
        s[t] += x;
        __syncthreads();
    }
    if (i < N_NODES) g_incl[i] = s[t];
    if (t == 1023) g_part[blockIdx.x] = s[t];
}

// parallel scan of block partials (49) and degree buckets (128), one block
__global__ void k_scanB() {
    __shared__ int sp[64];
    __shared__ int sb[NBUCKET];
    int t = threadIdx.x;  // 128 threads
    if (t < 64) sp[t] = (t < SCAN_BLOCKS) ? g_part[t] : 0;
    sb[t] = g_bucket[t];
    __syncthreads();
    for (int off = 1; off < 64; off <<= 1) {
        int v = (t < 64 && t >= off) ? sp[t - off] : 0;
        __syncthreads();
        if (t < 64) sp[t] += v;
        __syncthreads();
    }
    for (int off = 1; off < NBUCKET; off <<= 1) {
        int v = (t >= off) ? sb[t - off] : 0;
        __syncthreads();
        sb[t] += v;
        __syncthreads();
    }
    if (t < SCAN_BLOCKS) g_part[t] = (t == 0) ? 0 : sp[t - 1];  // exclusive
    if (t == 0) g_rowptr[N_NODES] = sp[SCAN_BLOCKS - 1];
    g_boff[t] = (t == 0) ? 0 : sb[t - 1];                        // exclusive
}

// rowptr finalize + degree-sorted permutation + reset cnt for scatter
__global__ void k_scanC() {
    int t = threadIdx.x;
    int i = blockIdx.x * 1024 + t;
    if (i < N_NODES) {
        int deg = g_cnt[i];
        g_rowptr[i] = g_incl[i] - deg + g_part[blockIdx.x];
        int b = deg < NBUCKET ? deg : NBUCKET - 1;
        int p = atomicAdd(&g_boff[b], 1);
        g_perm[p] = i;
        g_cnt[i] = 0;  // reset for scatter pass
    }
}

__global__ void k_scatter(const int* __restrict__ ei, const float* __restrict__ ea) {
    int e = blockIdx.x * blockDim.x + threadIdx.x;
    if (e < N_EDGES) {
        int s = ei[e];
        int d = ei[N_EDGES + e];
        int pos = g_rowptr[d] + atomicAdd(&g_cnt[d], 1);
        g_epack[pos] = make_float4(ea[3 * e], ea[3 * e + 1], ea[3 * e + 2], __int_as_float(s));
    }
}

// ---------------- layer-0 transform: x[N,9] -> xl(fp16), xr(fp32) ----------------
__global__ void k_gemm0(const float* __restrict__ x,
                        const float* __restrict__ Wl, const float* __restrict__ Wr,
                        const float* __restrict__ bl, const float* __restrict__ br) {
    int lane = threadIdx.x & 31;
    int row = blockIdx.x * 8 + (threadIdx.x >> 5);
    if (row >= N_NODES) return;
    const float2* Wl2 = (const float2*)Wl;
    const float2* Wr2 = (const float2*)Wr;
    float lx = 0.f, ly = 0.f, rx = 0.f, ry = 0.f;
#pragma unroll
    for (int k = 0; k < 9; ++k) {
        float xk = __ldg(&x[row * 9 + k]);
        float2 wl = Wl2[k * 32 + lane];
        float2 wr = Wr2[k * 32 + lane];
        lx += xk * wl.x; ly += xk * wl.y;
        rx += xk * wr.x; ry += xk * wr.y;
    }
    float2 b1 = ((const float2*)bl)[lane];
    float2 b2 = ((const float2*)br)[lane];
    ((__half2*)g_xlh)[row * 32 + lane] = __floats2half2_rn(lx + b1.x, ly + b1.y);
    ((float2*)g_xr)[row * 32 + lane] = make_float2(rx + b2.x, ry + b2.y);
}

// ---------------- h[N,64] @ (Wl|Wr)[64,64] -> xl(fp16), xr(fp32) ----------------
__global__ void k_gemm64(const float* __restrict__ Wl, const float* __restrict__ Wr,
                         const float* __restrict__ bl, const float* __restrict__ br) {
    __shared__ float sW[8192];
    int tid = threadIdx.x;
    for (int i = tid; i < 4096; i += 256) {
        sW[i] = Wl[i];
        sW[4096 + i] = Wr[i];
    }
    __syncthreads();
    int lane = tid & 31, warp = tid >> 5;
    int row0 = blockIdx.x * 32 + warp * 4;
    const float2* h2 = (const float2*)g_h;
    float2 hr[4];
#pragma unroll
    for (int r = 0; r < 4; ++r) {
        int row = row0 + r;
        hr[r] = (row < N_NODES) ? h2[row * 32 + lane] : make_float2(0.f, 0.f);
    }
    const float* Wp = sW + ((lane < 16) ? 0 : 4096);
    int c = (lane & 15) * 4;
    float4 acc[4];
#pragma unroll
    for (int r = 0; r < 4; ++r) acc[r] = make_float4(0.f, 0.f, 0.f, 0.f);
#pragma unroll 8
    for (int k = 0; k < 64; ++k) {
        float4 w4 = *(const float4*)&Wp[k * 64 + c];
#pragma unroll
        for (int r = 0; r < 4; ++r) {
            float hk = __shfl_sync(0xffffffffu, (k & 1) ? hr[r].y : hr[r].x, k >> 1);
            acc[r].x += hk * w4.x;
            acc[r].y += hk * w4.y;
            acc[r].z += hk * w4.z;
            acc[r].w += hk * w4.w;
        }
    }
    const float* bp = (lane < 16) ? bl : br;
    float4 b4 = make_float4(bp[c], bp[c + 1], bp[c + 2], bp[c + 3]);
    bool is_l = (lane < 16);
    int hl = lane & 15;
#pragma unroll
    for (int r = 0; r < 4; ++r) {
        int row = row0 + r;
        if (row < N_NODES) {
            float4 o = make_float4(acc[r].x + b4.x, acc[r].y + b4.y,
                                   acc[r].z + b4.z, acc[r].w + b4.w);
            if (is_l) {
                __half2 p0 = __floats2half2_rn(o.x, o.y);
                __half2 p1 = __floats2half2_rn(o.z, o.w);
                uint2 u;
                u.x = *(unsigned*)&p0;
                u.y = *(unsigned*)&p1;
                ((uint2*)g_xlh)[row * 16 + hl] = u;
            } else {
                ((float4*)g_xr)[row * 16 + hl] = o;
            }
        }
    }
}

// ---------------- GATv2 aggregation + BN + ReLU (+ optional fused mean-pool) ----
// 16 lanes per node (2 nodes per warp), 4 channels per lane; fp16 xl gather
// (one 128B line per node row); exp without max-shift (logits bounded).
__global__ void k_agg(const float* __restrict__ We, const float* __restrict__ att,
                      const float* __restrict__ bo,
                      const float* __restrict__ bng, const float* __restrict__ bnb,
                      const float* __restrict__ bnm, const float* __restrict__ bnv,
                      const int* __restrict__ batch) {  // non-null => fused pool, no g_h write
    int lane = threadIdx.x & 31;
    int hl = lane & 15;           // lane within half
    int half = lane >> 4;
    int wid = (blockIdx.x * (blockDim.x >> 5)) + (threadIdx.x >> 5);
    int slot = wid * 2 + half;    // 0..49999 (exact)
    int node = g_perm[slot];
    int beg = g_rowptr[node];
    int len = g_rowptr[node + 1] - beg;

    const uint2* xlh = (const uint2*)g_xlh;
    float4 xr4 = ((const float4*)g_xr)[node * 16 + hl];
    const float4* We4 = (const float4*)We;
    float4 w0 = We4[hl], w1 = We4[16 + hl], w2 = We4[32 + hl];
    float4 at4 = ((const float4*)att)[hl];

    int olen = __shfl_xor_sync(0xffffffffu, len, 16);
    int maxlen = len > olen ? len : olen;

    float z = 0.f;
    float4 acc = make_float4(0.f, 0.f, 0.f, 0.f);

    // 2-deep software pipeline: edge record one ahead, gather one ahead
    int last = len > 0 ? len - 1 : 0;
    int safe0 = beg < (N_EDGES - 1) ? beg : (N_EDGES - 1);  // deg-0 tail-node guard
    float4 E0, E1;
    uint2 u0;
    {
        E0 = g_epack[safe0];
        int s0 = __float_as_int(E0.w);
        u0 = xlh[s0 * 16 + hl];
        E1 = g_epack[safe0 + (1 < last ? 1 : 0)];
    }
    for (int i = 0; i < maxlen; ++i) {
        // prefetch next gather and next-next edge record
        int s1 = __float_as_int(E1.w);
        uint2 u1 = xlh[s1 * 16 + hl];
        int i2 = i + 2;
        int idx2 = safe0 + (i2 < last ? i2 : last);
        float4 E2 = g_epack[idx2];

        // unpack fp16 source row chunk
        float2 f01 = __half22float2(*(const __half2*)&u0.x);
        float2 f23 = __half22float2(*(const __half2*)&u0.y);

        // edge score (independent across iterations)
        float tx = f01.x + xr4.x + E0.x * w0.x + E0.y * w1.x + E0.z * w2.x;
        float ty = f01.y + xr4.y + E0.x * w0.y + E0.y * w1.y + E0.z * w2.y;
        float tz = f23.x + xr4.z + E0.x * w0.z + E0.y * w1.z + E0.z * w2.z;
        float tw = f23.y + xr4.w + E0.x * w0.w + E0.y * w1.w + E0.z * w2.w;
        tx = tx > 0.f ? tx : 0.2f * tx;
        ty = ty > 0.f ? ty : 0.2f * ty;
        tz = tz > 0.f ? tz : 0.2f * tz;
        tw = tw > 0.f ? tw : 0.2f * tw;
        float pt = tx * at4.x + ty * at4.y + tz * at4.z + tw * at4.w;
        pt += __shfl_xor_sync(0xffffffffu, pt, 8);
        pt += __shfl_xor_sync(0xffffffffu, pt, 4);
        pt += __shfl_xor_sync(0xffffffffu, pt, 2);
        pt += __shfl_xor_sync(0xffffffffu, pt, 1);

        float p = (i < len) ? __expf(pt) : 0.f;
        z += p;
        acc.x += p * f01.x;
        acc.y += p * f01.y;
        acc.z += p * f23.x;
        acc.w += p * f23.y;

        E0 = E1; u0 = u1; E1 = E2;
    }

    float4 o = make_float4(0.f, 0.f, 0.f, 0.f);
    if (z > 0.f) {
        float inv = 1.0f / z;
        o.x = acc.x * inv; o.y = acc.y * inv;
        o.z = acc.z * inv; o.w = acc.w * inv;
    }
    float4 bo4 = ((const float4*)bo)[hl];
    float4 gg = ((const float4*)bng)[hl];
    float4 bb = ((const float4*)bnb)[hl];
    float4 mm = ((const float4*)bnm)[hl];
    float4 vv = ((const float4*)bnv)[hl];
    o.x = fmaxf((o.x + bo4.x - mm.x) * (gg.x * rsqrtf(vv.x + 1e-5f)) + bb.x, 0.f);
    o.y = fmaxf((o.y + bo4.y - mm.y) * (gg.y * rsqrtf(vv.y + 1e-5f)) + bb.y, 0.f);
    o.z = fmaxf((o.z + bo4.z - mm.z) * (gg.z * rsqrtf(vv.z + 1e-5f)) + bb.z, 0.f);
    o.w = fmaxf((o.w + bo4.w - mm.w) * (gg.w * rsqrtf(vv.w + 1e-5f)) + bb.w, 0.f);

    if (batch == nullptr) {
        ((float4*)g_h)[node * 16 + hl] = o;
    } else {
        // fused global mean-pool contribution: dot(h_node, wvec)
        float4 wv = ((const float4*)g_wvec)[hl];
        float pt = o.x * wv.x + o.y * wv.y + o.z * wv.z + o.w * wv.w;
        pt += __shfl_xor_sync(0xffffffffu, pt, 8);
        pt += __shfl_xor_sync(0xffffffffu, pt, 4);
        pt += __shfl_xor_sync(0xffffffffu, pt, 2);
        pt += __shfl_xor_sync(0xffffffffu, pt, 1);
        if (hl == 0) {
            int g = batch[node];
            atomicAdd(&g_gsum[g], pt);
            atomicAdd(&g_gcnt[g], 1);
        }
    }
}

__global__ void k_head(float* __restrict__ out) {
    int g = blockIdx.x * blockDim.x + threadIdx.x;
    if (g < N_GRAPHS) out[g] = g_gsum[g] / fmaxf((float)g_gcnt[g], 1.0f) + g_cconst;
}

// ---------------- launch ----------------
extern "C" void kernel_launch(void* const* d_in, const int* in_sizes, int n_in,
                              void* d_out, int out_size) {
    const float* x     = (const float*)d_in[0];
    const float* ea    = (const float*)d_in[1];
    const float* Wl0   = (const float*)d_in[2];
    const float* Wr0   = (const float*)d_in[3];
    const float* bl0   = (const float*)d_in[4];
    const float* br0   = (const float*)d_in[5];
    const float* We0   = (const float*)d_in[6];
    const float* att0  = (const float*)d_in[7];
    const float* bo0   = (const float*)d_in[8];
    const float* Wl    = (const float*)d_in[9];
    const float* Wr    = (const float*)d_in[10];
    const float* bl    = (const float*)d_in[11];
    const float* br    = (const float*)d_in[12];
    const float* We    = (const float*)d_in[13];
    const float* att   = (const float*)d_in[14];
    const float* bo    = (const float*)d_in[15];
    const float* bng   = (const float*)d_in[16];
    const float* bnb   = (const float*)d_in[17];
    const float* bnm   = (const float*)d_in[18];
    const float* bnv   = (const float*)d_in[19];
    const float* Wjk   = (const float*)d_in[20];
    const float* bjk   = (const float*)d_in[21];
    const float* Whead = (const float*)d_in[22];
    const float* bhead = (const float*)d_in[23];
    const int*   ei    = (const int*)d_in[24];
    const int*   batch = (const int*)d_in[25];
    float* out = (float*)d_out;

    // CSR build (by dst) + degree-sorted permutation
    k_init<<<196, 256>>>(Wjk, bjk, Whead, bhead);
    k_hist<<<(N_EDGES + 1023) / 1024, 1024>>>(ei);
    k_scanA<<<SCAN_BLOCKS, 1024>>>();
    k_scanB<<<1, 128>>>();
    k_scanC<<<SCAN_BLOCKS, 1024>>>();
    k_scatter<<<(N_EDGES + 1023) / 1024, 1024>>>(ei, ea);

    // layer 0
    k_gemm0<<<6250, 256>>>(x, Wl0, Wr0, bl0, br0);
    k_agg<<<3125, 256>>>(We0, att0, bo0, bng, bnb, bnm, bnv, nullptr);

    // layers 1..4 (last layer fuses the mean-pool)
    for (int l = 0; l < 4; ++l) {
        k_gemm64<<<1563, 256>>>(Wl + l * 4096, Wr + l * 4096, bl + l * 64, br + l * 64);
        k_agg<<<3125, 256>>>(We + l * 192, att + l * 64, bo + l * 64,
                             bng + (l + 1) * 64, bnb + (l + 1) * 64,
                             bnm + (l + 1) * 64, bnv + (l + 1) * 64,
                             (l == 3) ? batch : nullptr);
    }

    // head
    k_head<<<2, 256>>>(out);
}

// round 11
// speedup vs baseline: 1.4726x; 1.4726x over previous
#include <cuda_runtime.h>
#include <cuda_fp16.h>

#define N_NODES 50000
#define N_EDGES 800000
#define N_GRAPHS 512
#define SCAN_BLOCKS 49  // ceil(50000/1024)
#define NBUCKET 128

// ---------------- scratch (static device globals; no allocs) ----------------
__device__ __align__(16) __half g_xlh[N_NODES * 64];   // fp16 mirror of xl (gathered in agg)
__device__ float g_xr[N_NODES * 64];
__device__ float g_h[N_NODES * 64];
__device__ int   g_rowptr[N_NODES + 1];
__device__ int   g_cnt[N_NODES];
__device__ int   g_incl[N_NODES];
__device__ int   g_part[64];
__device__ int   g_bucket[NBUCKET];   // degree histogram
__device__ int   g_boff[NBUCKET];     // degree bucket offsets (consumed atomically)
__device__ int   g_perm[N_NODES];     // nodes sorted by degree
__device__ float4 g_epack[N_EDGES];   // {ea0, ea1, ea2, __int_as_float(src)} sorted by dst
__device__ float g_wvec[64];
__device__ float g_cconst;
__device__ float g_gsum[N_GRAPHS];
__device__ int   g_gcnt[N_GRAPHS];

// ---------------- init: zero counters + precompute head vector ----------------
__global__ void k_init(const float* __restrict__ Wjk, const float* __restrict__ bjk,
                       const float* __restrict__ Whead, const float* __restrict__ bhead) {
    int i = blockIdx.x * blockDim.x + threadIdx.x;
    if (i < N_NODES) g_cnt[i] = 0;
    if (i < NBUCKET) g_bucket[i] = 0;
    if (i < N_GRAPHS) { g_gsum[i] = 0.f; g_gcnt[i] = 0; }
    if (i < 64) {
        float s = 0.f;
        for (int j = 0; j < 64; ++j) s += Wjk[i * 64 + j] * Whead[j];
        g_wvec[i] = s;
    }
    if (i == 0) {
        float s = 0.f;
        for (int j = 0; j < 64; ++j) s += bjk[j] * Whead[j];
        g_cconst = s + bhead[0];
    }
}

__global__ void k_hist(const int* __restrict__ ei) {
    int e = blockIdx.x * blockDim.x + threadIdx.x;
    if (e < N_EDGES) atomicAdd(&g_cnt[ei[N_EDGES + e]], 1);
}

// block-level inclusive scan of degrees + degree-bucket histogram
__global__ void k_scanA() {
    __shared__ int s[1024];
    int t = threadIdx.x;
    int i = blockIdx.x * 1024 + t;
    int v = (i < N_NODES) ? g_cnt[i] : 0;
    if (i < N_NODES) atomicAdd(&g_bucket[v < NBUCKET ? v : NBUCKET - 1], 1);
    s[t] = v;
    __syncthreads();
    for (int off = 1; off < 1024; off <<= 1) {
        int x = (t >= off) ? s[t - off] : 0;
        __syncthreads();
        s[t] += x;
        __syncthreads();
    }
    if (i < N_NODES) g_incl[i] = s[t];
    if (t == 1023) g_part[blockIdx.x] = s[t];
}

// parallel scan of block partials (49) and degree buckets (128), one block
__global__ void k_scanB() {
    __shared__ int sp[64];
    __shared__ int sb[NBUCKET];
    int t = threadIdx.x;  // 128 threads
    if (t < 64) sp[t] = (t < SCAN_BLOCKS) ? g_part[t] : 0;
    sb[t] = g_bucket[t];
    __syncthreads();
    for (int off = 1; off < 64; off <<= 1) {
        int v = (t < 64 && t >= off) ? sp[t - off] : 0;
        __syncthreads();
        if (t < 64) sp[t] += v;
        __syncthreads();
    }
    for (int off = 1; off < NBUCKET; off <<= 1) {
        int v = (t >= off) ? sb[t - off] : 0;
        __syncthreads();
        sb[t] += v;
        __syncthreads();
    }
    if (t < SCAN_BLOCKS) g_part[t] = (t == 0) ? 0 : sp[t - 1];  // exclusive
    if (t == 0) g_rowptr[N_NODES] = sp[SCAN_BLOCKS - 1];
    g_boff[t] = (t == 0) ? 0 : sb[t - 1];                        // exclusive
}

// rowptr finalize + degree-sorted permutation + reset cnt for scatter
__global__ void k_scanC() {
    int t = threadIdx.x;
    int i = blockIdx.x * 1024 + t;
    if (i < N_NODES) {
        int deg = g_cnt[i];
        g_rowptr[i] = g_incl[i] - deg + g_part[blockIdx.x];
        int b = deg < NBUCKET ? deg : NBUCKET - 1;
        int p = atomicAdd(&g_boff[b], 1);
        g_perm[p] = i;
        g_cnt[i] = 0;  // reset for scatter pass
    }
}

__global__ void k_scatter(const int* __restrict__ ei, const float* __restrict__ ea) {
    int e = blockIdx.x * blockDim.x + threadIdx.x;
    if (e < N_EDGES) {
        int s = ei[e];
        int d = ei[N_EDGES + e];
        int pos = g_rowptr[d] + atomicAdd(&g_cnt[d], 1);
        g_epack[pos] = make_float4(ea[3 * e], ea[3 * e + 1], ea[3 * e + 2], __int_as_float(s));
    }
}

// ---------------- layer-0 transform: x[N,9] -> xl(fp16), xr(fp32) ----------------
__global__ void k_gemm0(const float* __restrict__ x,
                        const float* __restrict__ Wl, const float* __restrict__ Wr,
                        const float* __restrict__ bl, const float* __restrict__ br) {
    int lane = threadIdx.x & 31;
    int row = blockIdx.x * 8 + (threadIdx.x >> 5);
    if (row >= N_NODES) return;
    const float2* Wl2 = (const float2*)Wl;
    const float2* Wr2 = (const float2*)Wr;
    float lx = 0.f, ly = 0.f, rx = 0.f, ry = 0.f;
#pragma unroll
    for (int k = 0; k < 9; ++k) {
        float xk = __ldg(&x[row * 9 + k]);
        float2 wl = Wl2[k * 32 + lane];
        float2 wr = Wr2[k * 32 + lane];
        lx += xk * wl.x; ly += xk * wl.y;
        rx += xk * wr.x; ry += xk * wr.y;
    }
    float2 b1 = ((const float2*)bl)[lane];
    float2 b2 = ((const float2*)br)[lane];
    ((__half2*)g_xlh)[row * 32 + lane] = __floats2half2_rn(lx + b1.x, ly + b1.y);
    ((float2*)g_xr)[row * 32 + lane] = make_float2(rx + b2.x, ry + b2.y);
}

// ---------------- h[N,64] @ (Wl|Wr)[64,64] -> xl(fp16), xr(fp32) ----------------
__global__ void k_gemm64(const float* __restrict__ Wl, const float* __restrict__ Wr,
                         const float* __restrict__ bl, const float* __restrict__ br) {
    __shared__ float sW[8192];
    int tid = threadIdx.x;
    for (int i = tid; i < 4096; i += 256) {
        sW[i] = Wl[i];
        sW[4096 + i] = Wr[i];
    }
    __syncthreads();
    int lane = tid & 31, warp = tid >> 5;
    int row0 = blockIdx.x * 32 + warp * 4;
    const float2* h2 = (const float2*)g_h;
    float2 hr[4];
#pragma unroll
    for (int r = 0; r < 4; ++r) {
        int row = row0 + r;
        hr[r] = (row < N_NODES) ? h2[row * 32 + lane] : make_float2(0.f, 0.f);
    }
    const float* Wp = sW + ((lane < 16) ? 0 : 4096);
    int c = (lane & 15) * 4;
    float4 acc[4];
#pragma unroll
    for (int r = 0; r < 4; ++r) acc[r] = make_float4(0.f, 0.f, 0.f, 0.f);
#pragma unroll 8
    for (int k = 0; k < 64; ++k) {
        float4 w4 = *(const float4*)&Wp[k * 64 + c];
#pragma unroll
        for (int r = 0; r < 4; ++r) {
            float hk = __shfl_sync(0xffffffffu, (k & 1) ? hr[r].y : hr[r].x, k >> 1);
            acc[r].x += hk * w4.x;
            acc[r].y += hk * w4.y;
            acc[r].z += hk * w4.z;
            acc[r].w += hk * w4.w;
        }
    }
    const float* bp = (lane < 16) ? bl : br;
    float4 b4 = make_float4(bp[c], bp[c + 1], bp[c + 2], bp[c + 3]);
    bool is_l = (lane < 16);
    int hl = lane & 15;
#pragma unroll
    for (int r = 0; r < 4; ++r) {
        int row = row0 + r;
        if (row < N_NODES) {
            float4 o = make_float4(acc[r].x + b4.x, acc[r].y + b4.y,
                                   acc[r].z + b4.z, acc[r].w + b4.w);
            if (is_l) {
                __half2 p0 = __floats2half2_rn(o.x, o.y);
                __half2 p1 = __floats2half2_rn(o.z, o.w);
                uint2 u;
                u.x = *(unsigned*)&p0;
                u.y = *(unsigned*)&p1;
                ((uint2*)g_xlh)[row * 16 + hl] = u;
            } else {
                ((float4*)g_xr)[row * 16 + hl] = o;
            }
        }
    }
}

// ---------------- GATv2 aggregation + BN + ReLU (+ optional fused mean-pool) ----
// 8 lanes per node (4 nodes per warp), 8 channels per lane, fp16 xl gather
// (one uint4 / lane -> one 128B line per gather), exp without max-shift.
__global__ void __launch_bounds__(256) k_agg(
                      const float* __restrict__ We, const float* __restrict__ att,
                      const float* __restrict__ bo,
                      const float* __restrict__ bng, const float* __restrict__ bnb,
                      const float* __restrict__ bnm, const float* __restrict__ bnv,
                      const int* __restrict__ batch) {  // non-null => fused pool, no g_h write
    int lane = threadIdx.x & 31;
    int ql = lane & 7;            // lane within 8-lane group
    int q  = lane >> 3;           // group id within warp (0..3)
    int wid = blockIdx.x * (blockDim.x >> 5) + (threadIdx.x >> 5);
    int slot = wid * 4 + q;       // 0..50015 (last warp partially OOB)
    bool live = slot < N_NODES;
    int node = live ? g_perm[slot] : 0;
    int beg = g_rowptr[node];
    int len = live ? (g_rowptr[node + 1] - beg) : 0;

    const uint4* xlh4 = (const uint4*)g_xlh;   // node row = 8 x uint4
    int f4b = ql * 2;  // float4 index base for this lane's 8 channels

    float w0v[8], w1v[8], w2v[8], atv[8], xrv[8];
#pragma unroll
    for (int j = 0; j < 2; ++j) {
        float4 a = ((const float4*)We)[0 * 16 + f4b + j];
        float4 b = ((const float4*)We)[1 * 16 + f4b + j];
        float4 c = ((const float4*)We)[2 * 16 + f4b + j];
        float4 d = ((const float4*)att)[f4b + j];
        float4 e = ((const float4*)g_xr)[node * 16 + f4b + j];
        w0v[j*4+0]=a.x; w0v[j*4+1]=a.y; w0v[j*4+2]=a.z; w0v[j*4+3]=a.w;
        w1v[j*4+0]=b.x; w1v[j*4+1]=b.y; w1v[j*4+2]=b.z; w1v[j*4+3]=b.w;
        w2v[j*4+0]=c.x; w2v[j*4+1]=c.y; w2v[j*4+2]=c.z; w2v[j*4+3]=c.w;
        atv[j*4+0]=d.x; atv[j*4+1]=d.y; atv[j*4+2]=d.z; atv[j*4+3]=d.w;
        xrv[j*4+0]=e.x; xrv[j*4+1]=e.y; xrv[j*4+2]=e.z; xrv[j*4+3]=e.w;
    }

    // warp-uniform trip count = max degree over the 4 groups (degree-sorted => tight)
    int m1 = len, o1;
    o1 = __shfl_xor_sync(0xffffffffu, m1, 8);  m1 = m1 > o1 ? m1 : o1;
    o1 = __shfl_xor_sync(0xffffffffu, m1, 16); m1 = m1 > o1 ? m1 : o1;
    int maxlen = m1;

    float z = 0.f;
    float acc[8];
#pragma unroll
    for (int k = 0; k < 8; ++k) acc[k] = 0.f;

    // 2-deep software pipeline: edge record one ahead, gather one ahead
    int last = len > 0 ? len - 1 : 0;
    int safe0 = beg < (N_EDGES - 1) ? beg : (N_EDGES - 1);
    float4 E0, E1;
    uint4 u0;
    {
        E0 = g_epack[safe0];
        int s0 = __float_as_int(E0.w);
        u0 = xlh4[s0 * 8 + ql];
        E1 = g_epack[safe0 + (1 < last ? 1 : 0)];
    }
    for (int i = 0; i < maxlen; ++i) {
        // prefetch next gather and next-next edge record
        int s1 = __float_as_int(E1.w);
        uint4 u1 = xlh4[s1 * 8 + ql];
        int i2 = i + 2;
        int idx2 = safe0 + (i2 < last ? i2 : last);
        float4 E2 = g_epack[idx2];

        // unpack fp16 source row chunk (8 channels)
        float f[8];
        {
            float2 t;
            t = __half22float2(*(const __half2*)&u0.x); f[0]=t.x; f[1]=t.y;
            t = __half22float2(*(const __half2*)&u0.y); f[2]=t.x; f[3]=t.y;
            t = __half22float2(*(const __half2*)&u0.z); f[4]=t.x; f[5]=t.y;
            t = __half22float2(*(const __half2*)&u0.w); f[6]=t.x; f[7]=t.y;
        }

        // edge score (independent across iterations and groups)
        float pt = 0.f;
#pragma unroll
        for (int k = 0; k < 8; ++k) {
            float t = f[k] + xrv[k] + E0.x * w0v[k] + E0.y * w1v[k] + E0.z * w2v[k];
            t = t > 0.f ? t : 0.2f * t;
            pt += t * atv[k];
        }
        pt += __shfl_xor_sync(0xffffffffu, pt, 4);
        pt += __shfl_xor_sync(0xffffffffu, pt, 2);
        pt += __shfl_xor_sync(0xffffffffu, pt, 1);

        float p = (i < len) ? __expf(pt) : 0.f;
        z += p;
#pragma unroll
        for (int k = 0; k < 8; ++k) acc[k] += p * f[k];

        E0 = E1; u0 = u1; E1 = E2;
    }

    float inv = (z > 0.f) ? (1.0f / z) : 0.f;
    float o[8];
#pragma unroll
    for (int j = 0; j < 2; ++j) {
        float4 bo4 = ((const float4*)bo)[f4b + j];
        float4 gg  = ((const float4*)bng)[f4b + j];
        float4 bb  = ((const float4*)bnb)[f4b + j];
        float4 mm  = ((const float4*)bnm)[f4b + j];
        float4 vv  = ((const float4*)bnv)[f4b + j];
        float bo_[4] = {bo4.x, bo4.y, bo4.z, bo4.w};
        float gg_[4] = {gg.x, gg.y, gg.z, gg.w};
        float bb_[4] = {bb.x, bb.y, bb.z, bb.w};
        float mm_[4] = {mm.x, mm.y, mm.z, mm.w};
        float vv_[4] = {vv.x, vv.y, vv.z, vv.w};
#pragma unroll
        for (int k = 0; k < 4; ++k) {
            int c = j * 4 + k;
            float val = acc[c] * inv + bo_[k];
            o[c] = fmaxf((val - mm_[k]) * (gg_[k] * rsqrtf(vv_[k] + 1e-5f)) + bb_[k], 0.f);
        }
    }

    if (batch == nullptr) {
        if (live) {
            ((float4*)g_h)[node * 16 + f4b]     = make_float4(o[0], o[1], o[2], o[3]);
            ((float4*)g_h)[node * 16 + f4b + 1] = make_float4(o[4], o[5], o[6], o[7]);
        }
    } else {
        // fused global mean-pool contribution: dot(h_node, wvec)
        float pt = 0.f;
#pragma unroll
        for (int j = 0; j < 2; ++j) {
            float4 wv = ((const float4*)g_wvec)[f4b + j];
            pt += o[j*4+0] * wv.x + o[j*4+1] * wv.y + o[j*4+2] * wv.z + o[j*4+3] * wv.w;
        }
        pt += __shfl_xor_sync(0xffffffffu, pt, 4);
        pt += __shfl_xor_sync(0xffffffffu, pt, 2);
        pt += __shfl_xor_sync(0xffffffffu, pt, 1);
        if (live && ql == 0) {
            int g = batch[node];
            atomicAdd(&g_gsum[g], pt);
            atomicAdd(&g_gcnt[g], 1);
        }
    }
}

__global__ void k_head(float* __restrict__ out) {
    int g = blockIdx.x * blockDim.x + threadIdx.x;
    if (g < N_GRAPHS) out[g] = g_gsum[g] / fmaxf((float)g_gcnt[g], 1.0f) + g_cconst;
}

// ---------------- launch ----------------
extern "C" void kernel_launch(void* const* d_in, const int* in_sizes, int n_in,
                              void* d_out, int out_size) {
    const float* x     = (const float*)d_in[0];
    const float* ea    = (const float*)d_in[1];
    const float* Wl0   = (const float*)d_in[2];
    const float* Wr0   = (const float*)d_in[3];
    const float* bl0   = (const float*)d_in[4];
    const float* br0   = (const float*)d_in[5];
    const float* We0   = (const float*)d_in[6];
    const float* att0  = (const float*)d_in[7];
    const float* bo0   = (const float*)d_in[8];
    const float* Wl    = (const float*)d_in[9];
    const float* Wr    = (const float*)d_in[10];
    const float* bl    = (const float*)d_in[11];
    const float* br    = (const float*)d_in[12];
    const float* We    = (const float*)d_in[13];
    const float* att   = (const float*)d_in[14];
    const float* bo    = (const float*)d_in[15];
    const float* bng   = (const float*)d_in[16];
    const float* bnb   = (const float*)d_in[17];
    const float* bnm   = (const float*)d_in[18];
    const float* bnv   = (const float*)d_in[19];
    const float* Wjk   = (const float*)d_in[20];
    const float* bjk   = (const float*)d_in[21];
    const float* Whead = (const float*)d_in[22];
    const float* bhead = (const float*)d_in[23];
    const int*   ei    = (const int*)d_in[24];
    const int*   batch = (const int*)d_in[25];
    float* out = (float*)d_out;

    // CSR build (by dst) + degree-sorted permutation
    k_init<<<196, 256>>>(Wjk, bjk, Whead, bhead);
    k_hist<<<(N_EDGES + 1023) / 1024, 1024>>>(ei);
    k_scanA<<<SCAN_BLOCKS, 1024>>>();
    k_scanB<<<1, 128>>>();
    k_scanC<<<SCAN_BLOCKS, 1024>>>();
    k_scatter<<<(N_EDGES + 1023) / 1024, 1024>>>(ei, ea);

    // layer 0
    k_gemm0<<<6250, 256>>>(x, Wl0, Wr0, bl0, br0);
    k_agg<<<1563, 256>>>(We0, att0, bo0, bng, bnb, bnm, bnv, nullptr);

    // layers 1..4 (last layer fuses the mean-pool)
    for (int l = 0; l < 4; ++l) {
        k_gemm64<<<1563, 256>>>(Wl + l * 4096, Wr + l * 4096, bl + l * 64, br + l * 64);
        k_agg<<<1563, 256>>>(We + l * 192, att + l * 64, bo + l * 64,
                             bng + (l + 1) * 64, bnb + (l + 1) * 64,
                             bnm + (l + 1) * 64, bnv + (l + 1) * 64,
                             (l == 3) ? batch : nullptr);
    }

    // head
    k_head<<<2, 256>>>(out);
}